// round 14
// baseline (speedup 1.0000x reference)
#include <cuda_runtime.h>
#include <cstdint>

// ---------------- problem constants ----------------
#define B_   8
#define C_   64
#define O_   256
#define TE_  128
#define GT_  256
#define A_   32
#define TILES_PER_B 257   // 32896 lower-tri pairs / 128 rows per tile (exact)
#define MT_  128          // packed pair-rows per CTA

// ---------------- device scratch (static; no allocations) ----------------
__device__ __align__(16) float g_uq  [B_ * O_ * GT_];            // u + q + b1 (2 MB)
__device__ __align__(16) float g_v   [B_ * O_ * GT_];            // v          (2 MB)
__device__ __align__(16) float g_part[B_ * TILES_PER_B * GT_];   // per-tile partials

// ---------------- helpers ----------------
__device__ __forceinline__ uint32_t f2tf32(float f) {
    uint32_t r;
    asm("cvt.rna.tf32.f32 %0, %1;" : "=r"(r) : "f"(f));
    return r;
}

__device__ __forceinline__ void mma_tf32(float& d0, float& d1, float& d2, float& d3,
                                         uint32_t a0, uint32_t a1, uint32_t a2, uint32_t a3,
                                         uint32_t b0, uint32_t b1) {
    asm volatile(
        "mma.sync.aligned.m16n8k8.row.col.f32.tf32.tf32.f32 "
        "{%0,%1,%2,%3}, {%4,%5,%6,%7}, {%8,%9}, {%0,%1,%2,%3};"
        : "+f"(d0), "+f"(d1), "+f"(d2), "+f"(d3)
        : "r"(a0), "r"(a1), "r"(a2), "r"(a3), "r"(b0), "r"(b1));
}

// triangular-number inversion: largest i with i(i+1)/2 <= p
__device__ __forceinline__ int tri_row(int p) {
    int i = (int)((sqrtf(8.0f * (float)p + 1.0f) - 1.0f) * 0.5f);
    while ((i + 1) * (i + 2) / 2 <= p) ++i;
    while (i * (i + 1) / 2 > p) --i;
    return i;
}

// ---------------- smem layout (floats) for main kernel ----------------
#define PA 260                          // Abuf row stride (260 % 32 == 4 -> conflict-free A frags)
#define PW 264                          // Wbuf row stride (264 % 32 == 8 -> conflict-free B frags)
#define SM_ABUF 0                       // 128 x 260 = 33280
#define SM_WBUF (MT_ * PA)              // 33280 : 2 x (32 x 264) double-buffered weight chunk
#define SM_BIAS (SM_WBUF + 2 * 32 * PW) // 50176 : 256
#define SM_COL  (SM_BIAS + 256)         // 50432 : 512
#define SM_FLOATS (SM_COL + 512)        // 50944 floats = 203776 bytes

// ============================================================================
// Kernel 0: u+q and v precompute (layer-1 factorization).
//   uq[b,i,n] = sum_c xo[b,i,c] W1[c,n] + sum_t code[b,t] W1[132+t,n] + b1[n]
//   v [b,i,n] = sum_c xo[b,i,c] W1[66+c,n]
// grid = 256 (8 batches x 32 groups of 8 objects), block = 256
// ============================================================================
__global__ void prep_kernel(const float* __restrict__ x, const float* __restrict__ code,
                            const float* __restrict__ w1, const float* __restrict__ b1) {
    __shared__ float xr[8][66];
    __shared__ float cbuf[TE_];
    const int b  = blockIdx.x >> 5;
    const int i0 = (blockIdx.x & 31) << 3;
    const int tid = threadIdx.x;

    for (int idx = tid; idx < 8 * 64; idx += 256) {
        int ch = idx >> 3, ii = idx & 7;
        xr[ii][ch] = x[(b * C_ + ch) * O_ + i0 + ii];
    }
    if (tid < 8) {
        int i = i0 + tid;
        xr[tid][64] = -1.0f + (2.0f / 15.0f) * (float)(i >> 4);   // yy
        xr[tid][65] = -1.0f + (2.0f / 15.0f) * (float)(i & 15);   // xx
    }
    if (tid < TE_) cbuf[tid] = code[b * TE_ + tid];
    __syncthreads();

    const int n = tid;   // 0..255 output feature
    float u[8], v[8];
#pragma unroll
    for (int ii = 0; ii < 8; ++ii) { u[ii] = 0.f; v[ii] = 0.f; }

#pragma unroll 2
    for (int c = 0; c < 66; ++c) {
        float wa = w1[c * GT_ + n];
        float wb = w1[(66 + c) * GT_ + n];
#pragma unroll
        for (int ii = 0; ii < 8; ++ii) {
            float xv = xr[ii][c];
            u[ii] += xv * wa;
            v[ii] += xv * wb;
        }
    }
    float cq = b1[n];
#pragma unroll 4
    for (int t = 0; t < TE_; ++t) cq += cbuf[t] * w1[(132 + t) * GT_ + n];

#pragma unroll
    for (int ii = 0; ii < 8; ++ii) {
        int row = b * O_ + i0 + ii;
        g_uq[row * GT_ + n] = u[ii] + cq;
        g_v [row * GT_ + n] = v[ii];
    }
}

// ============================================================================
// Fused 128x256x256 tf32 GEMM on smem Abuf, weights streamed (double-buffered)
// from global. 512 threads = 16 warps, 4(M) x 4(N) grid, warp tile 32x64,
// mma m16n8k8. A-fragments register-prefetched across the whole K loop.
// Output (ReLU applied) written back into Abuf, as tf32 bits or fp32.
// ============================================================================
template<bool TF32OUT>
__device__ __forceinline__ void gemm256(float* smem, const float4* __restrict__ gw4, int tid) {
    uint32_t* As = (uint32_t*)(smem + SM_ABUF);
    uint32_t* Ws = (uint32_t*)(smem + SM_WBUF);
    const float* bias = smem + SM_BIAS;

    const int lane = tid & 31;
    const int wid  = tid >> 5;
    const int g = lane >> 2;      // group id 0..7
    const int t = lane & 3;       // thread-in-group 0..3
    const int m0 = (wid & 3) * 32;
    const int n0 = (wid >> 2) * 64;

    float acc[2][8][4];
#pragma unroll
    for (int mt = 0; mt < 2; ++mt)
#pragma unroll
        for (int nt = 0; nt < 8; ++nt) {
            float be = bias[n0 + nt * 8 + 2 * t];
            float bo = bias[n0 + nt * 8 + 2 * t + 1];
            acc[mt][nt][0] = be; acc[mt][nt][1] = bo;
            acc[mt][nt][2] = be; acc[mt][nt][3] = bo;
        }

    // A-fragment row bases (u32 offsets into Abuf)
    uint32_t rA[4];
    rA[0] = (uint32_t)(m0 + g)      * PA;
    rA[1] = (uint32_t)(m0 + g + 8)  * PA;
    rA[2] = (uint32_t)(m0 + g + 16) * PA;
    rA[3] = (uint32_t)(m0 + g + 24) * PA;

    // global prefetch of weight chunk 0 (32 rows x 256 cols)
    float4 pf[4];
#pragma unroll
    for (int p = 0; p < 4; ++p) pf[p] = gw4[tid + p * 512];

    // A-fragment prefetch for k = 0 (Abuf stable for the whole GEMM)
    uint32_t afr[2][4];
#pragma unroll
    for (int mt = 0; mt < 2; ++mt) {
        afr[mt][0] = As[rA[mt * 2 + 0] + t];
        afr[mt][1] = As[rA[mt * 2 + 1] + t];
        afr[mt][2] = As[rA[mt * 2 + 0] + t + 4];
        afr[mt][3] = As[rA[mt * 2 + 1] + t + 4];
    }

#pragma unroll 1
    for (int c = 0; c < 8; ++c) {
        uint32_t* Wc = Ws + (c & 1) * 32 * PW;
        // store the prefetched chunk c (its buffer was last read at iter c-2,
        // separated by the barrier inside iter c-1)
#pragma unroll
        for (int p = 0; p < 4; ++p) {
            int f = tid + p * 512;
            int k = f >> 6, n4 = f & 63;
            uint4 o;
            o.x = f2tf32(pf[p].x); o.y = f2tf32(pf[p].y);
            o.z = f2tf32(pf[p].z); o.w = f2tf32(pf[p].w);
            *(uint4*)(Wc + k * PW + n4 * 4) = o;
        }
        if (c < 7) {   // issue global loads of chunk c+1 (consumed next iter)
#pragma unroll
            for (int p = 0; p < 4; ++p) pf[p] = gw4[(c + 1) * 2048 + tid + p * 512];
        }
        __syncthreads();

#pragma unroll
        for (int s = 0; s < 4; ++s) {
            const int klo = s * 8;            // chunk-local k for W
            // prefetch A-fragments for the next k-slice (pure Abuf, no barrier dep)
            uint32_t nafr[2][4];
            const int kn = c * 32 + klo + 8;
            if (kn < 256) {
#pragma unroll
                for (int mt = 0; mt < 2; ++mt) {
                    nafr[mt][0] = As[rA[mt * 2 + 0] + kn + t];
                    nafr[mt][1] = As[rA[mt * 2 + 1] + kn + t];
                    nafr[mt][2] = As[rA[mt * 2 + 0] + kn + t + 4];
                    nafr[mt][3] = As[rA[mt * 2 + 1] + kn + t + 4];
                }
            }
#pragma unroll
            for (int nt = 0; nt < 8; ++nt) {
                uint32_t b0 = Wc[(klo + t)     * PW + n0 + nt * 8 + g];
                uint32_t b1 = Wc[(klo + t + 4) * PW + n0 + nt * 8 + g];
                mma_tf32(acc[0][nt][0], acc[0][nt][1], acc[0][nt][2], acc[0][nt][3],
                         afr[0][0], afr[0][1], afr[0][2], afr[0][3], b0, b1);
                mma_tf32(acc[1][nt][0], acc[1][nt][1], acc[1][nt][2], acc[1][nt][3],
                         afr[1][0], afr[1][1], afr[1][2], afr[1][3], b0, b1);
            }
            if (kn < 256) {
#pragma unroll
                for (int mt = 0; mt < 2; ++mt)
#pragma unroll
                    for (int q = 0; q < 4; ++q) afr[mt][q] = nafr[mt][q];
            }
        }
    }

    __syncthreads();   // all Abuf reads done before epilogue overwrites it

    // epilogue: ReLU, write back into Abuf
#pragma unroll
    for (int mt = 0; mt < 2; ++mt) {
        int r0 = m0 + mt * 16 + g;
#pragma unroll
        for (int nt = 0; nt < 8; ++nt) {
            int col = n0 + nt * 8 + 2 * t;
            float v0 = fmaxf(acc[mt][nt][0], 0.f);
            float v1 = fmaxf(acc[mt][nt][1], 0.f);
            float v2 = fmaxf(acc[mt][nt][2], 0.f);
            float v3 = fmaxf(acc[mt][nt][3], 0.f);
            if (TF32OUT) {
                uint32_t* d0 = As + (uint32_t)r0 * PA + col;
                d0[0] = f2tf32(v0); d0[1] = f2tf32(v1);
                uint32_t* d1 = As + (uint32_t)(r0 + 8) * PA + col;
                d1[0] = f2tf32(v2); d1[1] = f2tf32(v3);
            } else {
                float* d0 = (float*)As + (uint32_t)r0 * PA + col;
                d0[0] = v0; d0[1] = v1;
                float* d1 = (float*)As + (uint32_t)(r0 + 8) * PA + col;
                d1[0] = v2; d1[1] = v3;
            }
        }
    }
}

// ============================================================================
// Kernel 1: fused per-tile pipeline over PACKED lower-triangular pairs.
// Tile t covers pair indices [t*128, t*128+128); pair p -> (i,j), j <= i.
// h1 rows built from uq[i] + v[j]; two tf32 GEMMs; full column sum -> g_part.
// grid = 8 * 257 = 2056, block = 512, dyn smem 203776 B.
// ============================================================================
__global__ void __launch_bounds__(512, 1)
main_kernel(const float* __restrict__ w2, const float* __restrict__ b2,
            const float* __restrict__ w3, const float* __restrict__ b3) {
    extern __shared__ float smem[];
    const int tid = threadIdx.x;
    const int b = blockIdx.x / TILES_PER_B;
    const int t = blockIdx.x - b * TILES_PER_B;
    const int p0 = t * MT_;

    if (tid < 256) smem[SM_BIAS + tid] = b2[tid];

    // ---- stage A: h1[r] = relu(uq[i_r] + v[j_r]) -> tf32 in Abuf ----
    {
        const float4* uq4 = (const float4*)(g_uq + (size_t)b * O_ * GT_);
        const float4* v4  = (const float4*)(g_v  + (size_t)b * O_ * GT_);
#pragma unroll 4
        for (int idx = tid; idx < MT_ * 64; idx += 512) {
            int r = idx >> 6, n4 = idx & 63;
            int p = p0 + r;
            int i = tri_row(p);
            int j = p - ((i * (i + 1)) >> 1);
            float4 uu = uq4[i * 64 + n4];
            float4 vv = v4 [j * 64 + n4];
            uint4 o;
            o.x = f2tf32(fmaxf(vv.x + uu.x, 0.f));
            o.y = f2tf32(fmaxf(vv.y + uu.y, 0.f));
            o.z = f2tf32(fmaxf(vv.z + uu.z, 0.f));
            o.w = f2tf32(fmaxf(vv.w + uu.w, 0.f));
            *(uint4*)(smem + SM_ABUF + r * PA + n4 * 4) = o;
        }
    }
    __syncthreads();

    // ---- g_theta layer 2: h2 = relu(h1 @ W2 + b2), tf32 back into Abuf ----
    gemm256<true>(smem, (const float4*)w2, tid);

    if (tid < 256) smem[SM_BIAS + tid] = b3[tid];
    __syncthreads();

    // ---- g_theta layer 3: rel = relu(h2 @ W3 + b3), fp32 into Abuf ----
    gemm256<false>(smem, (const float4*)w3, tid);
    __syncthreads();

    // ---- column reduction over all 128 packed rows ----
    {
        int half = tid >> 8;           // 0 or 1
        int n    = tid & 255;
        int rbeg = half * 64;
        float s = 0.f;
#pragma unroll 4
        for (int r = rbeg; r < rbeg + 64; ++r) s += smem[SM_ABUF + r * PA + n];
        smem[SM_COL + tid] = s;
    }
    __syncthreads();
    if (tid < 256)
        g_part[(size_t)(b * TILES_PER_B + t) * GT_ + tid] =
            smem[SM_COL + tid] + smem[SM_COL + 256 + tid];
}

// ============================================================================
// Kernel 2: per-batch reduction of tile partials + f_phi MLP.
// grid = 8, block = 256.
// ============================================================================
__global__ void tail_kernel(const float* __restrict__ fw1, const float* __restrict__ fb1,
                            const float* __restrict__ fw2, const float* __restrict__ fb2,
                            const float* __restrict__ fw3, const float* __restrict__ fb3,
                            float* __restrict__ out) {
    __shared__ float s0[256];
    __shared__ float s1[256];
    const int b = blockIdx.x;
    const int n = threadIdx.x;

    float s = 0.f;
    const float* p = g_part + (size_t)b * TILES_PER_B * GT_ + n;
#pragma unroll 4
    for (int t = 0; t < TILES_PER_B; ++t) s += p[(size_t)t * GT_];
    s0[n] = s;
    __syncthreads();

    float a1 = fb1[n];
#pragma unroll 8
    for (int k = 0; k < 256; ++k) a1 += s0[k] * fw1[k * 256 + n];
    s1[n] = fmaxf(a1, 0.f);
    __syncthreads();

    float a2 = fb2[n];
#pragma unroll 8
    for (int k = 0; k < 256; ++k) a2 += s1[k] * fw2[k * 256 + n];
    s0[n] = fmaxf(a2, 0.f);
    __syncthreads();

    if (n < A_) {
        float a3 = fb3[n];
#pragma unroll 8
        for (int k = 0; k < 256; ++k) a3 += s0[k] * fw3[k * A_ + n];
        out[b * A_ + n] = a3;
    }
}

// ============================================================================
// Host launcher
// ============================================================================
extern "C" void kernel_launch(void* const* d_in, const int* in_sizes, int n_in,
                              void* d_out, int out_size) {
    const float* x    = (const float*)d_in[0];
    const float* code = (const float*)d_in[1];
    const float* gw1  = (const float*)d_in[2];
    const float* gb1  = (const float*)d_in[3];
    const float* gw2  = (const float*)d_in[4];
    const float* gb2  = (const float*)d_in[5];
    const float* gw3  = (const float*)d_in[6];
    const float* gb3  = (const float*)d_in[7];
    const float* fw1  = (const float*)d_in[8];
    const float* fb1  = (const float*)d_in[9];
    const float* fw2  = (const float*)d_in[10];
    const float* fb2  = (const float*)d_in[11];
    const float* fw3  = (const float*)d_in[12];
    const float* fb3  = (const float*)d_in[13];
    float* out = (float*)d_out;
    (void)in_sizes; (void)n_in; (void)out_size;

    cudaFuncSetAttribute(main_kernel, cudaFuncAttributeMaxDynamicSharedMemorySize,
                         SM_FLOATS * (int)sizeof(float));

    prep_kernel<<<256, 256>>>(x, code, gw1, gb1);
    main_kernel<<<B_ * TILES_PER_B, 512, SM_FLOATS * sizeof(float)>>>(gw2, gb2, gw3, gb3);
    tail_kernel<<<B_, 256>>>(fw1, fb1, fw2, fb2, fw3, fb3, out);
}

// round 15
// speedup vs baseline: 1.0003x; 1.0003x over previous
#include <cuda_runtime.h>
#include <cstdint>

// ---------------- problem constants ----------------
#define B_   8
#define C_   64
#define O_   256
#define TE_  128
#define GT_  256
#define A_   32
#define TILES_PER_B 257   // 32896 lower-tri pairs / 128 rows per tile (exact)
#define MT_  128          // packed pair-rows per CTA

// ---------------- device scratch (static; no allocations) ----------------
__device__ __align__(16) float g_uq  [B_ * O_ * GT_];            // u + q + b1 (2 MB)
__device__ __align__(16) float g_v   [B_ * O_ * GT_];            // v          (2 MB)
__device__ __align__(16) float g_part[B_ * TILES_PER_B * GT_];   // per-tile partials

// ---------------- helpers ----------------
__device__ __forceinline__ uint32_t f2tf32(float f) {
    uint32_t r;
    asm("cvt.rna.tf32.f32 %0, %1;" : "=r"(r) : "f"(f));
    return r;
}

__device__ __forceinline__ void mma_tf32(float& d0, float& d1, float& d2, float& d3,
                                         uint32_t a0, uint32_t a1, uint32_t a2, uint32_t a3,
                                         uint32_t b0, uint32_t b1) {
    asm volatile(
        "mma.sync.aligned.m16n8k8.row.col.f32.tf32.tf32.f32 "
        "{%0,%1,%2,%3}, {%4,%5,%6,%7}, {%8,%9}, {%0,%1,%2,%3};"
        : "+f"(d0), "+f"(d1), "+f"(d2), "+f"(d3)
        : "r"(a0), "r"(a1), "r"(a2), "r"(a3), "r"(b0), "r"(b1));
}

// triangular-number inversion: largest i with i(i+1)/2 <= p
__device__ __forceinline__ int tri_row(int p) {
    int i = (int)((sqrtf(8.0f * (float)p + 1.0f) - 1.0f) * 0.5f);
    while ((i + 1) * (i + 2) / 2 <= p) ++i;
    while (i * (i + 1) / 2 > p) --i;
    return i;
}

// ---------------- smem layout (floats) for main kernel ----------------
#define PA 260                          // Abuf row stride (260 % 32 == 4 -> conflict-free A frags)
#define PW 264                          // Wbuf row stride (264 % 32 == 8 -> conflict-free B frags)
#define SM_ABUF 0                       // 128 x 260 = 33280
#define SM_WBUF (MT_ * PA)              // 33280 : 2 x (32 x 264) double-buffered weight chunk
#define SM_BIAS (SM_WBUF + 2 * 32 * PW) // 50176 : 256
#define SM_COL  (SM_BIAS + 256)         // 50432 : 512
#define SM_FLOATS (SM_COL + 512)        // 50944 floats = 203776 bytes

// ============================================================================
// Kernel 0: u+q and v precompute (layer-1 factorization).
//   uq[b,i,n] = sum_c xo[b,i,c] W1[c,n] + sum_t code[b,t] W1[132+t,n] + b1[n]
//   v [b,i,n] = sum_c xo[b,i,c] W1[66+c,n]
// grid = 256 (8 batches x 32 groups of 8 objects), block = 256
// ============================================================================
__global__ void prep_kernel(const float* __restrict__ x, const float* __restrict__ code,
                            const float* __restrict__ w1, const float* __restrict__ b1) {
    __shared__ float xr[8][66];
    __shared__ float cbuf[TE_];
    const int b  = blockIdx.x >> 5;
    const int i0 = (blockIdx.x & 31) << 3;
    const int tid = threadIdx.x;

    for (int idx = tid; idx < 8 * 64; idx += 256) {
        int ch = idx >> 3, ii = idx & 7;
        xr[ii][ch] = x[(b * C_ + ch) * O_ + i0 + ii];
    }
    if (tid < 8) {
        int i = i0 + tid;
        xr[tid][64] = -1.0f + (2.0f / 15.0f) * (float)(i >> 4);   // yy
        xr[tid][65] = -1.0f + (2.0f / 15.0f) * (float)(i & 15);   // xx
    }
    if (tid < TE_) cbuf[tid] = code[b * TE_ + tid];
    __syncthreads();

    const int n = tid;   // 0..255 output feature
    float u[8], v[8];
#pragma unroll
    for (int ii = 0; ii < 8; ++ii) { u[ii] = 0.f; v[ii] = 0.f; }

#pragma unroll 2
    for (int c = 0; c < 66; ++c) {
        float wa = w1[c * GT_ + n];
        float wb = w1[(66 + c) * GT_ + n];
#pragma unroll
        for (int ii = 0; ii < 8; ++ii) {
            float xv = xr[ii][c];
            u[ii] += xv * wa;
            v[ii] += xv * wb;
        }
    }
    float cq = b1[n];
#pragma unroll 4
    for (int t = 0; t < TE_; ++t) cq += cbuf[t] * w1[(132 + t) * GT_ + n];

#pragma unroll
    for (int ii = 0; ii < 8; ++ii) {
        int row = b * O_ + i0 + ii;
        g_uq[row * GT_ + n] = u[ii] + cq;
        g_v [row * GT_ + n] = v[ii];
    }
}

// ============================================================================
// Fused 128x256x256 tf32 GEMM on smem Abuf, weights streamed (double-buffered)
// from global. 512 threads = 16 warps, 4(M) x 4(N) grid, warp tile 32x64,
// mma m16n8k8. A-fragments register-prefetched across the whole K loop.
// Output (ReLU applied) written back into Abuf, as tf32 bits or fp32.
// ============================================================================
template<bool TF32OUT>
__device__ __forceinline__ void gemm256(float* smem, const float4* __restrict__ gw4, int tid) {
    uint32_t* As = (uint32_t*)(smem + SM_ABUF);
    uint32_t* Ws = (uint32_t*)(smem + SM_WBUF);
    const float* bias = smem + SM_BIAS;

    const int lane = tid & 31;
    const int wid  = tid >> 5;
    const int g = lane >> 2;      // group id 0..7
    const int t = lane & 3;       // thread-in-group 0..3
    const int m0 = (wid & 3) * 32;
    const int n0 = (wid >> 2) * 64;

    float acc[2][8][4];
#pragma unroll
    for (int mt = 0; mt < 2; ++mt)
#pragma unroll
        for (int nt = 0; nt < 8; ++nt) {
            float be = bias[n0 + nt * 8 + 2 * t];
            float bo = bias[n0 + nt * 8 + 2 * t + 1];
            acc[mt][nt][0] = be; acc[mt][nt][1] = bo;
            acc[mt][nt][2] = be; acc[mt][nt][3] = bo;
        }

    // A-fragment row bases (u32 offsets into Abuf)
    uint32_t rA[4];
    rA[0] = (uint32_t)(m0 + g)      * PA;
    rA[1] = (uint32_t)(m0 + g + 8)  * PA;
    rA[2] = (uint32_t)(m0 + g + 16) * PA;
    rA[3] = (uint32_t)(m0 + g + 24) * PA;

    // global prefetch of weight chunk 0 (32 rows x 256 cols)
    float4 pf[4];
#pragma unroll
    for (int p = 0; p < 4; ++p) pf[p] = gw4[tid + p * 512];

    // A-fragment prefetch for k = 0 (Abuf stable for the whole GEMM)
    uint32_t afr[2][4];
#pragma unroll
    for (int mt = 0; mt < 2; ++mt) {
        afr[mt][0] = As[rA[mt * 2 + 0] + t];
        afr[mt][1] = As[rA[mt * 2 + 1] + t];
        afr[mt][2] = As[rA[mt * 2 + 0] + t + 4];
        afr[mt][3] = As[rA[mt * 2 + 1] + t + 4];
    }

#pragma unroll 1
    for (int c = 0; c < 8; ++c) {
        uint32_t* Wc = Ws + (c & 1) * 32 * PW;
        // store the prefetched chunk c (its buffer was last read at iter c-2,
        // separated by the barrier inside iter c-1)
#pragma unroll
        for (int p = 0; p < 4; ++p) {
            int f = tid + p * 512;
            int k = f >> 6, n4 = f & 63;
            uint4 o;
            o.x = f2tf32(pf[p].x); o.y = f2tf32(pf[p].y);
            o.z = f2tf32(pf[p].z); o.w = f2tf32(pf[p].w);
            *(uint4*)(Wc + k * PW + n4 * 4) = o;
        }
        if (c < 7) {   // issue global loads of chunk c+1 (consumed next iter)
#pragma unroll
            for (int p = 0; p < 4; ++p) pf[p] = gw4[(c + 1) * 2048 + tid + p * 512];
        }
        __syncthreads();

#pragma unroll
        for (int s = 0; s < 4; ++s) {
            const int klo = s * 8;            // chunk-local k for W
            // prefetch A-fragments for the next k-slice (pure Abuf, no barrier dep)
            uint32_t nafr[2][4];
            const int kn = c * 32 + klo + 8;
            if (kn < 256) {
#pragma unroll
                for (int mt = 0; mt < 2; ++mt) {
                    nafr[mt][0] = As[rA[mt * 2 + 0] + kn + t];
                    nafr[mt][1] = As[rA[mt * 2 + 1] + kn + t];
                    nafr[mt][2] = As[rA[mt * 2 + 0] + kn + t + 4];
                    nafr[mt][3] = As[rA[mt * 2 + 1] + kn + t + 4];
                }
            }
#pragma unroll
            for (int nt = 0; nt < 8; ++nt) {
                uint32_t b0 = Wc[(klo + t)     * PW + n0 + nt * 8 + g];
                uint32_t b1 = Wc[(klo + t + 4) * PW + n0 + nt * 8 + g];
                mma_tf32(acc[0][nt][0], acc[0][nt][1], acc[0][nt][2], acc[0][nt][3],
                         afr[0][0], afr[0][1], afr[0][2], afr[0][3], b0, b1);
                mma_tf32(acc[1][nt][0], acc[1][nt][1], acc[1][nt][2], acc[1][nt][3],
                         afr[1][0], afr[1][1], afr[1][2], afr[1][3], b0, b1);
            }
            if (kn < 256) {
#pragma unroll
                for (int mt = 0; mt < 2; ++mt)
#pragma unroll
                    for (int q = 0; q < 4; ++q) afr[mt][q] = nafr[mt][q];
            }
        }
    }

    __syncthreads();   // all Abuf reads done before epilogue overwrites it

    // epilogue: ReLU, write back into Abuf
#pragma unroll
    for (int mt = 0; mt < 2; ++mt) {
        int r0 = m0 + mt * 16 + g;
#pragma unroll
        for (int nt = 0; nt < 8; ++nt) {
            int col = n0 + nt * 8 + 2 * t;
            float v0 = fmaxf(acc[mt][nt][0], 0.f);
            float v1 = fmaxf(acc[mt][nt][1], 0.f);
            float v2 = fmaxf(acc[mt][nt][2], 0.f);
            float v3 = fmaxf(acc[mt][nt][3], 0.f);
            if (TF32OUT) {
                uint32_t* d0 = As + (uint32_t)r0 * PA + col;
                d0[0] = f2tf32(v0); d0[1] = f2tf32(v1);
                uint32_t* d1 = As + (uint32_t)(r0 + 8) * PA + col;
                d1[0] = f2tf32(v2); d1[1] = f2tf32(v3);
            } else {
                float* d0 = (float*)As + (uint32_t)r0 * PA + col;
                d0[0] = v0; d0[1] = v1;
                float* d1 = (float*)As + (uint32_t)(r0 + 8) * PA + col;
                d1[0] = v2; d1[1] = v3;
            }
        }
    }
}

// ============================================================================
// Kernel 1: fused per-tile pipeline over PACKED lower-triangular pairs.
// Tile t covers pair indices [t*128, t*128+128); pair p -> (i,j), j <= i.
// h1 rows built from uq[i] + v[j]; two tf32 GEMMs; full column sum -> g_part.
// grid = 8 * 257 = 2056, block = 512, dyn smem 203776 B.
// ============================================================================
__global__ void __launch_bounds__(512, 1)
main_kernel(const float* __restrict__ w2, const float* __restrict__ b2,
            const float* __restrict__ w3, const float* __restrict__ b3) {
    extern __shared__ float smem[];
    const int tid = threadIdx.x;
    const int b = blockIdx.x / TILES_PER_B;
    const int t = blockIdx.x - b * TILES_PER_B;
    const int p0 = t * MT_;

    if (tid < 256) smem[SM_BIAS + tid] = b2[tid];

    // ---- stage A: h1[r] = relu(uq[i_r] + v[j_r]) -> tf32 in Abuf ----
    {
        const float4* uq4 = (const float4*)(g_uq + (size_t)b * O_ * GT_);
        const float4* v4  = (const float4*)(g_v  + (size_t)b * O_ * GT_);
#pragma unroll 4
        for (int idx = tid; idx < MT_ * 64; idx += 512) {
            int r = idx >> 6, n4 = idx & 63;
            int p = p0 + r;
            int i = tri_row(p);
            int j = p - ((i * (i + 1)) >> 1);
            float4 uu = uq4[i * 64 + n4];
            float4 vv = v4 [j * 64 + n4];
            uint4 o;
            o.x = f2tf32(fmaxf(vv.x + uu.x, 0.f));
            o.y = f2tf32(fmaxf(vv.y + uu.y, 0.f));
            o.z = f2tf32(fmaxf(vv.z + uu.z, 0.f));
            o.w = f2tf32(fmaxf(vv.w + uu.w, 0.f));
            *(uint4*)(smem + SM_ABUF + r * PA + n4 * 4) = o;
        }
    }
    __syncthreads();

    // ---- g_theta layer 2: h2 = relu(h1 @ W2 + b2), tf32 back into Abuf ----
    gemm256<true>(smem, (const float4*)w2, tid);

    if (tid < 256) smem[SM_BIAS + tid] = b3[tid];
    __syncthreads();

    // ---- g_theta layer 3: rel = relu(h2 @ W3 + b3), fp32 into Abuf ----
    gemm256<false>(smem, (const float4*)w3, tid);
    __syncthreads();

    // ---- column reduction over all 128 packed rows ----
    {
        int half = tid >> 8;           // 0 or 1
        int n    = tid & 255;
        int rbeg = half * 64;
        float s = 0.f;
#pragma unroll 4
        for (int r = rbeg; r < rbeg + 64; ++r) s += smem[SM_ABUF + r * PA + n];
        smem[SM_COL + tid] = s;
    }
    __syncthreads();
    if (tid < 256)
        g_part[(size_t)(b * TILES_PER_B + t) * GT_ + tid] =
            smem[SM_COL + tid] + smem[SM_COL + 256 + tid];
}

// ============================================================================
// Kernel 2: per-batch reduction of tile partials + f_phi MLP.
// grid = 8, block = 256.
// ============================================================================
__global__ void tail_kernel(const float* __restrict__ fw1, const float* __restrict__ fb1,
                            const float* __restrict__ fw2, const float* __restrict__ fb2,
                            const float* __restrict__ fw3, const float* __restrict__ fb3,
                            float* __restrict__ out) {
    __shared__ float s0[256];
    __shared__ float s1[256];
    const int b = blockIdx.x;
    const int n = threadIdx.x;

    float s = 0.f;
    const float* p = g_part + (size_t)b * TILES_PER_B * GT_ + n;
#pragma unroll 4
    for (int t = 0; t < TILES_PER_B; ++t) s += p[(size_t)t * GT_];
    s0[n] = s;
    __syncthreads();

    float a1 = fb1[n];
#pragma unroll 8
    for (int k = 0; k < 256; ++k) a1 += s0[k] * fw1[k * 256 + n];
    s1[n] = fmaxf(a1, 0.f);
    __syncthreads();

    float a2 = fb2[n];
#pragma unroll 8
    for (int k = 0; k < 256; ++k) a2 += s1[k] * fw2[k * 256 + n];
    s0[n] = fmaxf(a2, 0.f);
    __syncthreads();

    if (n < A_) {
        float a3 = fb3[n];
#pragma unroll 8
        for (int k = 0; k < 256; ++k) a3 += s0[k] * fw3[k * A_ + n];
        out[b * A_ + n] = a3;
    }
}

// ============================================================================
// Host launcher
// ============================================================================
extern "C" void kernel_launch(void* const* d_in, const int* in_sizes, int n_in,
                              void* d_out, int out_size) {
    const float* x    = (const float*)d_in[0];
    const float* code = (const float*)d_in[1];
    const float* gw1  = (const float*)d_in[2];
    const float* gb1  = (const float*)d_in[3];
    const float* gw2  = (const float*)d_in[4];
    const float* gb2  = (const float*)d_in[5];
    const float* gw3  = (const float*)d_in[6];
    const float* gb3  = (const float*)d_in[7];
    const float* fw1  = (const float*)d_in[8];
    const float* fb1  = (const float*)d_in[9];
    const float* fw2  = (const float*)d_in[10];
    const float* fb2  = (const float*)d_in[11];
    const float* fw3  = (const float*)d_in[12];
    const float* fb3  = (const float*)d_in[13];
    float* out = (float*)d_out;
    (void)in_sizes; (void)n_in; (void)out_size;

    cudaFuncSetAttribute(main_kernel, cudaFuncAttributeMaxDynamicSharedMemorySize,
                         SM_FLOATS * (int)sizeof(float));

    prep_kernel<<<256, 256>>>(x, code, gw1, gb1);
    main_kernel<<<B_ * TILES_PER_B, 512, SM_FLOATS * sizeof(float)>>>(gw2, gb2, gw3, gb3);
    tail_kernel<<<B_, 256>>>(fw1, fb1, fw2, fb2, fw3, fb3, out);
}

// round 16
// speedup vs baseline: 1.6436x; 1.6431x over previous
#include <cuda_runtime.h>
#include <cstdint>

// ---------------- problem constants ----------------
#define B_   8
#define C_   64
#define O_   256
#define TE_  128
#define GT_  256
#define A_   32
#define TILES_PER_B 257   // 32896 lower-tri pairs / 128 rows per tile (exact)
#define MT_  128          // packed pair-rows per CTA

// ---------------- device scratch (static; no allocations) ----------------
__device__ __align__(16) float    g_uq  [B_ * O_ * GT_];            // u + q + b1 (2 MB)
__device__ __align__(16) float    g_v   [B_ * O_ * GT_];            // v          (2 MB)
__device__ __align__(16) float    g_cq  [B_ * GT_];                 // code part
__device__ __align__(16) float    g_part[B_ * TILES_PER_B * GT_];   // per-tile partials
__device__ __align__(16) float    g_red [B_ * 8 * GT_];             // pre-reduced partials
__device__ __align__(16) uint32_t g_w2h [128 * GT_];                // W2 as half2 k-pairs [k2][n]
__device__ __align__(16) uint32_t g_w3h [128 * GT_];                // W3 as half2 k-pairs [k2][n]

// ---------------- helpers ----------------
// pack two floats into f16x2 (lo = first arg, hi = second arg)
__device__ __forceinline__ uint32_t f2h2(float lo, float hi) {
    uint32_t r;
    asm("cvt.rn.f16x2.f32 %0, %1, %2;" : "=r"(r) : "f"(hi), "f"(lo));
    return r;
}

__device__ __forceinline__ void mma_f16(float* d,
                                        uint32_t a0, uint32_t a1, uint32_t a2, uint32_t a3,
                                        uint32_t b0, uint32_t b1) {
    asm volatile(
        "mma.sync.aligned.m16n8k16.row.col.f32.f16.f16.f32 "
        "{%0,%1,%2,%3}, {%4,%5,%6,%7}, {%8,%9}, {%0,%1,%2,%3};"
        : "+f"(d[0]), "+f"(d[1]), "+f"(d[2]), "+f"(d[3])
        : "r"(a0), "r"(a1), "r"(a2), "r"(a3), "r"(b0), "r"(b1));
}

// triangular-number inversion: largest i with i(i+1)/2 <= p
__device__ __forceinline__ int tri_row(int p) {
    int i = (int)((sqrtf(8.0f * (float)p + 1.0f) - 1.0f) * 0.5f);
    while ((i + 1) * (i + 2) / 2 <= p) ++i;
    while (i * (i + 1) / 2 > p) --i;
    return i;
}

// ---------------- smem layout (4B units) for main kernel ----------------
#define PA2 132                         // Abuf row stride in half2 (132 % 32 == 4 -> conflict-free)
#define PW2 264                         // Wbuf k2-row stride in half2 (264 % 32 == 8 -> conflict-free)
#define SM_ABUF 0                       // 128 x 132 half2 = 16896 u32
#define SM_WBUF 16896                   // 2 x 16 x 264 half2 = 8448 u32 (double-buffered chunk)
#define SM_BIAS 25344                   // 256 f32
#define SM_COL  25600                   // 4 x 256 f32
#define SM_FLOATS 26624                 // 106496 bytes

// ============================================================================
// Kernel A: cq[b,n] = b1[n] + sum_t code[b,t] * W1[132+t, n].  grid=8, block=256
// ============================================================================
__global__ void cq_kernel(const float* __restrict__ code, const float* __restrict__ w1,
                          const float* __restrict__ b1) {
    __shared__ float cbuf[TE_];
    const int b = blockIdx.x, n = threadIdx.x;
    if (n < TE_) cbuf[n] = code[b * TE_ + n];
    __syncthreads();
    float cq = b1[n];
#pragma unroll 8
    for (int t = 0; t < TE_; ++t) cq += cbuf[t] * w1[(132 + t) * GT_ + n];
    g_cq[b * GT_ + n] = cq;
}

// ============================================================================
// Kernel B: u+q and v precompute (layer-1 factorization), 4 objects per CTA.
// grid = 512 (8 batches x 64 groups), block = 256
// ============================================================================
__global__ void prep_kernel(const float* __restrict__ x, const float* __restrict__ w1) {
    __shared__ float xr[4][66];
    const int b  = blockIdx.x >> 6;
    const int i0 = (blockIdx.x & 63) << 2;
    const int tid = threadIdx.x;

    { int ch = tid >> 2, ii = tid & 3;
      xr[ii][ch] = x[(b * C_ + ch) * O_ + i0 + ii]; }
    if (tid < 4) {
        int i = i0 + tid;
        xr[tid][64] = -1.0f + (2.0f / 15.0f) * (float)(i >> 4);   // yy
        xr[tid][65] = -1.0f + (2.0f / 15.0f) * (float)(i & 15);   // xx
    }
    __syncthreads();

    const int n = tid;
    float u[4] = {0.f, 0.f, 0.f, 0.f}, v[4] = {0.f, 0.f, 0.f, 0.f};
#pragma unroll 2
    for (int c = 0; c < 66; ++c) {
        float wa = w1[c * GT_ + n];
        float wb = w1[(66 + c) * GT_ + n];
#pragma unroll
        for (int ii = 0; ii < 4; ++ii) {
            float xv = xr[ii][c];
            u[ii] += xv * wa;
            v[ii] += xv * wb;
        }
    }
    float cq = g_cq[b * GT_ + n];
#pragma unroll
    for (int ii = 0; ii < 4; ++ii) {
        int row = b * O_ + i0 + ii;
        g_uq[row * GT_ + n] = u[ii] + cq;
        g_v [row * GT_ + n] = v[ii];
    }
}

// ============================================================================
// Kernel C: convert W2/W3 (f32 [k][n]) -> half2 k-pairs [k2][n]. grid=256, block=256
// ============================================================================
__global__ void wcvt_kernel(const float* __restrict__ w2, const float* __restrict__ w3) {
    int idx = blockIdx.x * 256 + threadIdx.x;       // 0..65535
    const float* w  = (idx < 32768) ? w2 : w3;
    uint32_t* dst   = (idx < 32768) ? g_w2h : g_w3h;
    int id = idx & 32767;
    int k2 = id >> 8, n = id & 255;
    dst[id] = f2h2(w[(2 * k2) * GT_ + n], w[(2 * k2 + 1) * GT_ + n]);
}

// ============================================================================
// Fused 128x256x256 fp16 GEMM (f32 accum) on smem Abuf (half2 k-pairs),
// weights streamed as pre-converted half2 (double-buffered 32-k chunks).
// 512 threads = 16 warps, 4(M) x 4(N), warp tile 32x64, mma m16n8k16.
// REDUCE=false: relu -> half2 back into Abuf.  REDUCE=true: relu + column sums
// into smem colsum[4][256] (no writeback).
// ============================================================================
template<bool REDUCE>
__device__ __forceinline__ void gemm256h(float* smem, const uint4* __restrict__ gwh, int tid) {
    uint32_t* As = (uint32_t*)(smem + SM_ABUF);
    uint32_t* Ws = (uint32_t*)(smem + SM_WBUF);
    const float* bias = smem + SM_BIAS;

    const int lane = tid & 31;
    const int wid  = tid >> 5;
    const int g = lane >> 2;      // group id 0..7
    const int t = lane & 3;       // thread-in-group 0..3
    const int m0 = (wid & 3) * 32;
    const int n0 = (wid >> 2) * 64;

    float acc[2][8][4];
#pragma unroll
    for (int mt = 0; mt < 2; ++mt)
#pragma unroll
        for (int nt = 0; nt < 8; ++nt) {
            float be = bias[n0 + nt * 8 + 2 * t];
            float bo = bias[n0 + nt * 8 + 2 * t + 1];
            acc[mt][nt][0] = be; acc[mt][nt][1] = bo;
            acc[mt][nt][2] = be; acc[mt][nt][3] = bo;
        }

    uint32_t rA[4];
    rA[0] = (uint32_t)(m0 + g)      * PA2;
    rA[1] = (uint32_t)(m0 + g + 8)  * PA2;
    rA[2] = (uint32_t)(m0 + g + 16) * PA2;
    rA[3] = (uint32_t)(m0 + g + 24) * PA2;

    // prefetch weight chunk 0 (16 k2-rows x 256 n half2 = 1024 uint4)
    uint4 pf[2];
    pf[0] = gwh[tid];
    pf[1] = gwh[tid + 512];

    // A-fragment prefetch for k16-slice 0
    uint32_t afr[2][4];
#pragma unroll
    for (int mt = 0; mt < 2; ++mt) {
        afr[mt][0] = As[rA[mt * 2 + 0] + t];
        afr[mt][1] = As[rA[mt * 2 + 1] + t];
        afr[mt][2] = As[rA[mt * 2 + 0] + t + 4];
        afr[mt][3] = As[rA[mt * 2 + 1] + t + 4];
    }

#pragma unroll 1
    for (int c = 0; c < 8; ++c) {
        uint32_t* Wc = Ws + (c & 1) * (16 * PW2);
        // store chunk c (its buffer was last read in iter c-2; iter c-1's barrier separates)
#pragma unroll
        for (int p = 0; p < 2; ++p) {
            int f = tid + p * 512;
            *(uint4*)(Wc + (f >> 6) * PW2 + (f & 63) * 4) = pf[p];
        }
        if (c < 7) {
            pf[0] = gwh[(c + 1) * 1024 + tid];
            pf[1] = gwh[(c + 1) * 1024 + tid + 512];
        }
        __syncthreads();

#pragma unroll
        for (int s = 0; s < 2; ++s) {
            const int klo2 = s * 8;               // chunk-local k2
            uint32_t nafr[2][4];
            const int kn2 = c * 16 + klo2 + 8;    // next slice base (half2 units)
            if (kn2 < 128) {
#pragma unroll
                for (int mt = 0; mt < 2; ++mt) {
                    nafr[mt][0] = As[rA[mt * 2 + 0] + kn2 + t];
                    nafr[mt][1] = As[rA[mt * 2 + 1] + kn2 + t];
                    nafr[mt][2] = As[rA[mt * 2 + 0] + kn2 + t + 4];
                    nafr[mt][3] = As[rA[mt * 2 + 1] + kn2 + t + 4];
                }
            }
#pragma unroll
            for (int nt = 0; nt < 8; ++nt) {
                uint32_t b0 = Wc[(klo2 + t)     * PW2 + n0 + nt * 8 + g];
                uint32_t b1 = Wc[(klo2 + t + 4) * PW2 + n0 + nt * 8 + g];
                mma_f16(acc[0][nt], afr[0][0], afr[0][1], afr[0][2], afr[0][3], b0, b1);
                mma_f16(acc[1][nt], afr[1][0], afr[1][1], afr[1][2], afr[1][3], b0, b1);
            }
            if (kn2 < 128) {
#pragma unroll
                for (int mt = 0; mt < 2; ++mt)
#pragma unroll
                    for (int q = 0; q < 4; ++q) afr[mt][q] = nafr[mt][q];
            }
        }
    }

    __syncthreads();   // all Abuf reads done

    if (REDUCE) {
        // column sums straight from accumulators; deterministic fixed-order reduce
        float* cs = smem + SM_COL + (wid & 3) * 256;
#pragma unroll
        for (int nt = 0; nt < 8; ++nt) {
            float c0 = fmaxf(acc[0][nt][0], 0.f) + fmaxf(acc[0][nt][2], 0.f)
                     + fmaxf(acc[1][nt][0], 0.f) + fmaxf(acc[1][nt][2], 0.f);
            float c1 = fmaxf(acc[0][nt][1], 0.f) + fmaxf(acc[0][nt][3], 0.f)
                     + fmaxf(acc[1][nt][1], 0.f) + fmaxf(acc[1][nt][3], 0.f);
#pragma unroll
            for (int off = 4; off < 32; off <<= 1) {
                c0 += __shfl_xor_sync(0xffffffffu, c0, off);
                c1 += __shfl_xor_sync(0xffffffffu, c1, off);
            }
            if (lane < 4) {   // t == lane
                cs[n0 + nt * 8 + 2 * t]     = c0;
                cs[n0 + nt * 8 + 2 * t + 1] = c1;
            }
        }
    } else {
        // relu -> half2 back into Abuf
#pragma unroll
        for (int mt = 0; mt < 2; ++mt) {
            int r0 = m0 + mt * 16 + g;
#pragma unroll
            for (int nt = 0; nt < 8; ++nt) {
                int c2 = (n0 >> 1) + nt * 4 + t;   // half2 column index
                As[(uint32_t)r0 * PA2 + c2] =
                    f2h2(fmaxf(acc[mt][nt][0], 0.f), fmaxf(acc[mt][nt][1], 0.f));
                As[(uint32_t)(r0 + 8) * PA2 + c2] =
                    f2h2(fmaxf(acc[mt][nt][2], 0.f), fmaxf(acc[mt][nt][3], 0.f));
            }
        }
    }
}

// ============================================================================
// Kernel D: fused per-tile pipeline over PACKED lower-triangular pairs.
// grid = 8 * 257 = 2056, block = 512, dyn smem 106496 B.
// ============================================================================
__global__ void __launch_bounds__(512, 1)
main_kernel(const float* __restrict__ b2, const float* __restrict__ b3) {
    extern __shared__ float smem[];
    const int tid = threadIdx.x;
    const int b  = blockIdx.x / TILES_PER_B;
    const int tt = blockIdx.x - b * TILES_PER_B;
    const int p0 = tt * MT_;

    if (tid < 256) smem[SM_BIAS + tid] = b2[tid];

    // ---- stage A: h1[r] = relu(uq[i_r] + v[j_r]) -> half2 in Abuf ----
    {
        const float4* uq4 = (const float4*)(g_uq + (size_t)b * O_ * GT_);
        const float4* v4  = (const float4*)(g_v  + (size_t)b * O_ * GT_);
        uint32_t* As = (uint32_t*)smem;
#pragma unroll 4
        for (int idx = tid; idx < MT_ * 64; idx += 512) {
            int r = idx >> 6, n4 = idx & 63;
            int p = p0 + r;
            int i = tri_row(p);
            int j = p - ((i * (i + 1)) >> 1);
            float4 uu = uq4[i * 64 + n4];
            float4 vv = v4 [j * 64 + n4];
            uint2 o;
            o.x = f2h2(fmaxf(uu.x + vv.x, 0.f), fmaxf(uu.y + vv.y, 0.f));
            o.y = f2h2(fmaxf(uu.z + vv.z, 0.f), fmaxf(uu.w + vv.w, 0.f));
            *(uint2*)(As + r * PA2 + n4 * 2) = o;
        }
    }
    __syncthreads();

    // ---- g_theta layer 2: h2 = relu(h1 @ W2 + b2) -> half2 into Abuf ----
    gemm256h<false>(smem, (const uint4*)g_w2h, tid);

    if (tid < 256) smem[SM_BIAS + tid] = b3[tid];
    __syncthreads();

    // ---- g_theta layer 3 + column reduction from accumulators ----
    gemm256h<true>(smem, (const uint4*)g_w3h, tid);
    __syncthreads();

    if (tid < 256) {
        const float* cs = smem + SM_COL;
        g_part[(size_t)(b * TILES_PER_B + tt) * GT_ + tid] =
            cs[tid] + cs[256 + tid] + cs[512 + tid] + cs[768 + tid];
    }
}

// ============================================================================
// Kernel E: pre-reduce tile partials. grid = 64 (8b x 8 slices), block = 256.
// ============================================================================
__global__ void reduce_kernel() {
    const int b = blockIdx.x >> 3, s = blockIdx.x & 7, n = threadIdx.x;
    const int t0  = s * 32 + (s > 0 ? 1 : 0);
    const int cnt = (s == 0) ? 33 : 32;
    float acc = 0.f;
    const float* p = g_part + ((size_t)b * TILES_PER_B + t0) * GT_ + n;
#pragma unroll 4
    for (int t = 0; t < cnt; ++t) acc += p[(size_t)t * GT_];
    g_red[(b * 8 + s) * GT_ + n] = acc;
}

// ============================================================================
// Kernel F: final per-batch sum + f_phi MLP. grid = 8, block = 256.
// ============================================================================
__global__ void tail_kernel(const float* __restrict__ fw1, const float* __restrict__ fb1,
                            const float* __restrict__ fw2, const float* __restrict__ fb2,
                            const float* __restrict__ fw3, const float* __restrict__ fb3,
                            float* __restrict__ out) {
    __shared__ float s0[256];
    __shared__ float s1[256];
    const int b = blockIdx.x;
    const int n = threadIdx.x;

    float s = 0.f;
    const float* p = g_red + (size_t)b * 8 * GT_ + n;
#pragma unroll
    for (int t = 0; t < 8; ++t) s += p[t * GT_];
    s0[n] = s;
    __syncthreads();

    float a1 = fb1[n];
#pragma unroll 8
    for (int k = 0; k < 256; ++k) a1 += s0[k] * fw1[k * 256 + n];
    s1[n] = fmaxf(a1, 0.f);
    __syncthreads();

    float a2 = fb2[n];
#pragma unroll 8
    for (int k = 0; k < 256; ++k) a2 += s1[k] * fw2[k * 256 + n];
    s0[n] = fmaxf(a2, 0.f);
    __syncthreads();

    if (n < A_) {
        float a3 = fb3[n];
#pragma unroll 8
        for (int k = 0; k < 256; ++k) a3 += s0[k] * fw3[k * A_ + n];
        out[b * A_ + n] = a3;
    }
}

// ============================================================================
// Host launcher
// ============================================================================
extern "C" void kernel_launch(void* const* d_in, const int* in_sizes, int n_in,
                              void* d_out, int out_size) {
    const float* x    = (const float*)d_in[0];
    const float* code = (const float*)d_in[1];
    const float* gw1  = (const float*)d_in[2];
    const float* gb1  = (const float*)d_in[3];
    const float* gw2  = (const float*)d_in[4];
    const float* gb2  = (const float*)d_in[5];
    const float* gw3  = (const float*)d_in[6];
    const float* gb3  = (const float*)d_in[7];
    const float* fw1  = (const float*)d_in[8];
    const float* fb1  = (const float*)d_in[9];
    const float* fw2  = (const float*)d_in[10];
    const float* fb2  = (const float*)d_in[11];
    const float* fw3  = (const float*)d_in[12];
    const float* fb3  = (const float*)d_in[13];
    float* out = (float*)d_out;
    (void)in_sizes; (void)n_in; (void)out_size;

    cudaFuncSetAttribute(main_kernel, cudaFuncAttributeMaxDynamicSharedMemorySize,
                         SM_FLOATS * (int)sizeof(float));

    wcvt_kernel<<<256, 256>>>(gw2, gw3);
    cq_kernel<<<B_, 256>>>(code, gw1, gb1);
    prep_kernel<<<512, 256>>>(x, gw1);
    main_kernel<<<B_ * TILES_PER_B, 512, SM_FLOATS * sizeof(float)>>>(gb2, gb3);
    reduce_kernel<<<64, 256>>>();
    tail_kernel<<<B_, 256>>>(fw1, fb1, fw2, fb2, fw3, fb3, out);
}